// round 2
// baseline (speedup 1.0000x reference)
#include <cuda_runtime.h>
#include <cuda_bf16.h>

// Cosine similarity per row: out[i] = dot(q_i, d_i) / (||q_i|| * ||d_i||)
// N = 262144 rows, D = 256 fp32. One warp per row; each lane handles 8
// elements via two float4 loads per input tensor.

#define D_DIM 256
#define THREADS_PER_BLOCK 256
#define WARPS_PER_BLOCK (THREADS_PER_BLOCK / 32)

__global__ __launch_bounds__(THREADS_PER_BLOCK, 8)
void cosine_sim_kernel(const float* __restrict__ q,
                       const float* __restrict__ d,
                       float* __restrict__ out,
                       int n_rows) {
    const int warp_id = (blockIdx.x * WARPS_PER_BLOCK) + (threadIdx.x >> 5);
    const int lane = threadIdx.x & 31;
    if (warp_id >= n_rows) return;

    // Row base in float4 units: D_DIM/4 = 64 float4 per row.
    const float4* q4 = reinterpret_cast<const float4*>(q) + (size_t)warp_id * (D_DIM / 4);
    const float4* d4 = reinterpret_cast<const float4*>(d) + (size_t)warp_id * (D_DIM / 4);

    // Each lane: float4 at [lane] and [lane + 32] for both tensors.
    // Issue all 4 loads up front (MLP=4) before consuming.
    float4 qa = q4[lane];
    float4 qb = q4[lane + 32];
    float4 da = d4[lane];
    float4 db = d4[lane + 32];

    float dot = qa.x * da.x + qa.y * da.y + qa.z * da.z + qa.w * da.w
              + qb.x * db.x + qb.y * db.y + qb.z * db.z + qb.w * db.w;
    float qq  = qa.x * qa.x + qa.y * qa.y + qa.z * qa.z + qa.w * qa.w
              + qb.x * qb.x + qb.y * qb.y + qb.z * qb.z + qb.w * qb.w;
    float dd  = da.x * da.x + da.y * da.y + da.z * da.z + da.w * da.w
              + db.x * db.x + db.y * db.y + db.z * db.z + db.w * db.w;

    // Warp butterfly reduction of the three partial sums.
    #pragma unroll
    for (int off = 16; off > 0; off >>= 1) {
        dot += __shfl_xor_sync(0xFFFFFFFFu, dot, off);
        qq  += __shfl_xor_sync(0xFFFFFFFFu, qq,  off);
        dd  += __shfl_xor_sync(0xFFFFFFFFu, dd,  off);
    }

    if (lane == 0) {
        out[warp_id] = dot * rsqrtf(qq * dd);
    }
}

extern "C" void kernel_launch(void* const* d_in, const int* in_sizes, int n_in,
                              void* d_out, int out_size) {
    const float* q = (const float*)d_in[0];
    const float* d = (const float*)d_in[1];
    float* out = (float*)d_out;

    // in_sizes[0] = N * D elements
    const int n_rows = in_sizes[0] / D_DIM;
    const int blocks = (n_rows + WARPS_PER_BLOCK - 1) / WARPS_PER_BLOCK;

    cosine_sim_kernel<<<blocks, THREADS_PER_BLOCK>>>(q, d, out, n_rows);
}